// round 4
// baseline (speedup 1.0000x reference)
#include <cuda_runtime.h>
#include <math.h>

// ---------------------------------------------------------------------------
// YOLOv3 loss, decomposed:
//   obj_loss  = sum_all_cells 0.5*softplus(po)                (baseline)
//             + sum_obj_cells [0.5*softplus(po) - po]         (correction)
//   box_loss  = 5 * sum_obj [ bce(px,txf)+bce(py,tyf)+(pw-tw)^2+(ph-th)^2 ]
//   cls_loss  = sum_obj sum_c [ softplus(pc_c) - tcls_c * pc_c ]
// with bce(x,t) = softplus(x) - t*x, tcls = UNION of colliding targets' classes,
// and box targets from the LAST (highest-index) target scattered to a cell.
// ---------------------------------------------------------------------------

#define NUM_CLASSES 25
#define CH (5 + NUM_CLASSES)   // 30
#define MAXB 64
#define G0 13
#define G1 26
#define G2 52
// total cells for B=64: 64*3*(169+676+2704) = 681408
#define GMAX (MAXB * 3 * (G0*G0 + G1*G1 + G2*G2))

__constant__ float c_anchors[3][3][2] = {
    {{116.f, 90.f}, {156.f, 198.f}, {373.f, 326.f}},
    {{ 30.f, 61.f}, { 62.f,  45.f}, { 59.f, 119.f}},
    {{ 10.f, 13.f}, { 16.f,  30.f}, { 33.f,  23.f}}};
__constant__ int c_grid[3] = {G0, G1, G2};

// Scratch: zero-initialized at module load; kernels restore zeros before exit,
// so every graph replay sees the same (clean) initial state.
__device__ unsigned int g_winner[GMAX];   // 0 = empty, else (target_idx + 1)
__device__ unsigned int g_clsmask[GMAX];  // bit c set => class c targeted here
__device__ float        g_acc[3];         // box, obj, cls partial sums

static __device__ __forceinline__ float softplusf(float x) {
    return fmaxf(x, 0.f) + log1pf(expf(-fabsf(x)));
}

// Decode one (target n, scale s): cell index within scale, global key, targets.
// Returns valid flag (matches JAX OOB-scatter drop semantics).
static __device__ __forceinline__ bool decode_target(
    const float* __restrict__ tg, int n, int s, int B,
    int* key, int* cell, int* cid_out,
    float* txf, float* tyf, float* twt, float* tht)
{
    const float* t = tg + (size_t)n * 6;
    int   g  = c_grid[s];
    float gf = (float)g;
    int   bi  = (int)t[0];
    *cid_out  = (int)t[1];
    float tx_ = t[2] * gf, ty_ = t[3] * gf;
    float tw_ = t[4] * gf, th_ = t[5] * gf;
    float fx = floorf(tx_), fy = floorf(ty_);
    int gx = (int)fx, gy = (int)fy;
    bool valid = (gx >= 0) & (gx < g) & (gy >= 0) & (gy < g);

    // argmax IoU over 3 anchors (strict > keeps first max, like jnp.argmax)
    float bestIou = -1.f, bsaw = 1.f, bsah = 1.f;
    int   best = 0;
#pragma unroll
    for (int a = 0; a < 3; a++) {
        float saw = c_anchors[s][a][0] / gf;
        float sah = c_anchors[s][a][1] / gf;
        float inter = fminf(tw_, saw) * fminf(th_, sah);
        float uni   = tw_ * th_ + saw * sah - inter;
        float iou   = inter / (uni + 1e-9f);
        if (iou > bestIou) { bestIou = iou; best = a; bsaw = saw; bsah = sah; }
    }

    int c = ((bi * 3 + best) * g + gy) * g + gx;
    int base = (s == 0) ? 0
             : (s == 1) ? B * 3 * (G0 * G0)
                        : B * 3 * (G0 * G0) + B * 3 * (G1 * G1);
    *cell = c;
    *key  = base + c;
    *txf  = tx_ - fx;
    *tyf  = ty_ - fy;
    *twt  = logf(tw_ / bsaw + 1e-16f);
    *tht  = logf(th_ / bsah + 1e-16f);
    return valid;
}

// K1: target scatter pass (winner + class mask), also zero the accumulators.
__global__ void k_pass1(const float* __restrict__ tg, int B, int N) {
    int i = blockIdx.x * blockDim.x + threadIdx.x;
    if (i < 3) g_acc[i] = 0.f;
    if (i >= 3 * N) return;
    int s = i / N, n = i % N;
    int key, cell, cid; float a, b, c, d;
    bool valid = decode_target(tg, n, s, B, &key, &cell, &cid, &a, &b, &c, &d);
    if (valid) {
        atomicMax(&g_winner[key], (unsigned)(n + 1));
        atomicOr(&g_clsmask[key], 1u << cid);
    }
}

// K2: fused big reduction. Items [0, total_cells): no-obj baseline over po.
// Items [total_cells, total_cells + 3N): per-target obj-cell corrections.
__global__ void __launch_bounds__(256)
k_main(const float* __restrict__ p0, const float* __restrict__ p1,
       const float* __restrict__ p2, const float* __restrict__ tg,
       int B, int N, int cells0, int cells1, int cells2)
{
    const int total_cells = cells0 + cells1 + cells2;
    const int total_work  = total_cells + 3 * N;
    float lbox = 0.f, lobj = 0.f, lcls = 0.f;

    for (int i = blockIdx.x * blockDim.x + threadIdx.x; i < total_work;
         i += gridDim.x * blockDim.x) {
        if (i < total_cells) {
            const float* p; int c;
            if (i < cells0)               { p = p0; c = i; }
            else if (i < cells0 + cells1) { p = p1; c = i - cells0; }
            else                          { p = p2; c = i - cells0 - cells1; }
            float po = __ldg(p + (size_t)c * CH + 4);   // one 32B sector per cell
            lobj += 0.5f * softplusf(po);
        } else {
            int j = i - total_cells;
            int s = j / N, n = j % N;
            int key, cell, cid; float txf, tyf, twt, tht;
            bool valid = decode_target(tg, n, s, B, &key, &cell, &cid,
                                       &txf, &tyf, &twt, &tht);
            if (valid && g_winner[key] == (unsigned)(n + 1)) {
                const float* p = ((s == 0) ? p0 : (s == 1) ? p1 : p2)
                                 + (size_t)cell * CH;
                float px = p[0], py = p[1], pw = p[2], ph = p[3], po = p[4];
                lbox += 5.0f * ((softplusf(px) - txf * px)
                              + (softplusf(py) - tyf * py)
                              + (pw - twt) * (pw - twt)
                              + (ph - tht) * (ph - tht));
                lobj += 0.5f * softplusf(po) - po;   // full-obj minus baseline
                unsigned m = g_clsmask[key];
                float cs = 0.f;
#pragma unroll
                for (int c = 0; c < NUM_CLASSES; c++) {
                    float pc = p[5 + c];
                    cs += softplusf(pc) - (((m >> c) & 1u) ? pc : 0.f);
                }
                lcls += cs;
            }
        }
    }

    // block reduction of 3 partials
    __shared__ float sb[256], so[256], sc[256];
    int t = threadIdx.x;
    sb[t] = lbox; so[t] = lobj; sc[t] = lcls;
    __syncthreads();
    for (int off = 128; off > 0; off >>= 1) {
        if (t < off) { sb[t] += sb[t + off]; so[t] += so[t + off]; sc[t] += sc[t + off]; }
        __syncthreads();
    }
    if (t == 0) {
        atomicAdd(&g_acc[0], sb[0]);
        atomicAdd(&g_acc[1], so[0]);
        atomicAdd(&g_acc[2], sc[0]);
    }
}

// K3: restore scratch to zero (only touched entries) + write the 4 outputs.
__global__ void k_final(const float* __restrict__ tg, int B, int N,
                        float* __restrict__ out) {
    int i = blockIdx.x * blockDim.x + threadIdx.x;
    if (i < 3 * N) {
        int s = i / N, n = i % N;
        int key, cell, cid; float a, b, c, d;
        bool valid = decode_target(tg, n, s, B, &key, &cell, &cid, &a, &b, &c, &d);
        if (valid) { g_winner[key] = 0u; g_clsmask[key] = 0u; }
    } else if (i == 3 * N) {
        float bx = g_acc[0], ob = g_acc[1], cl = g_acc[2];
        out[0] = bx + ob + cl;
        out[1] = bx;
        out[2] = ob;
        out[3] = cl;
    }
}

extern "C" void kernel_launch(void* const* d_in, const int* in_sizes, int n_in,
                              void* d_out, int out_size) {
    const float* p0 = (const float*)d_in[0];  // pred_large  [B,3,13,13,30]
    const float* p1 = (const float*)d_in[1];  // pred_medium [B,3,26,26,30]
    const float* p2 = (const float*)d_in[2];  // pred_small  [B,3,52,52,30]
    const float* tg = (const float*)d_in[3];  // targets     [N,6]
    float* out = (float*)d_out;

    int B = in_sizes[0] / (3 * G0 * G0 * CH);
    int N = in_sizes[3] / 6;

    int cells0 = B * 3 * G0 * G0;
    int cells1 = B * 3 * G1 * G1;
    int cells2 = B * 3 * G2 * G2;

    int nt = 3 * N;
    k_pass1<<<(nt + 255) / 256, 256>>>(tg, B, N);

    int work = cells0 + cells1 + cells2 + nt;
    int blocks = (work + 255) / 256;
    if (blocks > 1184) blocks = 1184;   // grid-stride; ~8 waves worth of blocks
    k_main<<<blocks, 256>>>(p0, p1, p2, tg, B, N, cells0, cells1, cells2);

    k_final<<<(nt + 1 + 255) / 256, 256>>>(tg, B, N, out);
}

// round 7
// speedup vs baseline: 1.1366x; 1.1366x over previous
#include <cuda_runtime.h>
#include <math.h>

// ---------------------------------------------------------------------------
// YOLOv3 loss, single fused kernel:
//   phase 0 (first SB blocks): scatter winner/classmask for targets
//   phase 1 (all blocks):      no-obj baseline 0.5*softplus(po) over all cells
//   phase 2 (first SB blocks): wait doorbell, per-target obj-cell corrections,
//                              winner zeroes its scratch entries (self-clean)
//   phase 3 (all blocks):      block reduce -> g_acc; last block writes out
//                              and resets g_acc/g_done/g_sem
// ---------------------------------------------------------------------------

#define NUM_CLASSES 25
#define CH (5 + NUM_CLASSES)   // 30
#define MAXB 64
#define G0 13
#define G1 26
#define G2 52
#define GMAX (MAXB * 3 * (G0*G0 + G1*G1 + G2*G2))   // 681408

#define NB 740     // 740*256*4 = 757,760 >= 681,408 cells -> single wave, ILP4
#define NT 256

__constant__ float c_anchors[3][3][2] = {
    {{116.f, 90.f}, {156.f, 198.f}, {373.f, 326.f}},
    {{ 30.f, 61.f}, { 62.f,  45.f}, { 59.f, 119.f}},
    {{ 10.f, 13.f}, { 16.f,  30.f}, { 33.f,  23.f}}};
__constant__ int c_grid[3] = {G0, G1, G2};

// Zero-initialized at module load; kernel restores zeros every run.
__device__ unsigned int g_winner[GMAX];   // 0 = empty, else (target_idx + 1)
__device__ unsigned int g_clsmask[GMAX];  // bit c set => class c targeted here
__device__ float        g_acc[3];         // box, obj, cls partial sums
__device__ unsigned int g_sem;            // scatter-done doorbell
__device__ unsigned int g_done;           // finished-block counter

static __device__ __forceinline__ float softplusf(float x) {
    // |rel err| ~2^-21 from fast intrinsics; tolerance is 1e-3.
    return fmaxf(x, 0.f) + __logf(1.f + __expf(-fabsf(x)));
}

// Decode one (target n, scale s). Returns valid flag (JAX OOB-drop semantics).
static __device__ __forceinline__ bool decode_target(
    const float* __restrict__ tg, int n, int s, int B,
    int* key, int* cell, int* cid_out,
    float* txf, float* tyf, float* twt, float* tht)
{
    const float* t = tg + (size_t)n * 6;
    int   g  = c_grid[s];
    float gf = (float)g;
    int   bi  = (int)t[0];
    *cid_out  = (int)t[1];
    float tx_ = t[2] * gf, ty_ = t[3] * gf;
    float tw_ = t[4] * gf, th_ = t[5] * gf;
    float fx = floorf(tx_), fy = floorf(ty_);
    int gx = (int)fx, gy = (int)fy;
    bool valid = (gx >= 0) & (gx < g) & (gy >= 0) & (gy < g);

    float bestIou = -1.f, bsaw = 1.f, bsah = 1.f;
    int   best = 0;
#pragma unroll
    for (int a = 0; a < 3; a++) {
        float saw = c_anchors[s][a][0] / gf;
        float sah = c_anchors[s][a][1] / gf;
        float inter = fminf(tw_, saw) * fminf(th_, sah);
        float uni   = tw_ * th_ + saw * sah - inter;
        float iou   = inter / (uni + 1e-9f);
        if (iou > bestIou) { bestIou = iou; best = a; bsaw = saw; bsah = sah; }
    }

    int c = ((bi * 3 + best) * g + gy) * g + gx;
    int base = (s == 0) ? 0
             : (s == 1) ? B * 3 * (G0 * G0)
                        : B * 3 * (G0 * G0) + B * 3 * (G1 * G1);
    *cell = c;
    *key  = base + c;
    *txf  = tx_ - fx;
    *tyf  = ty_ - fy;
    *twt  = logf(tw_ / bsaw + 1e-16f);
    *tht  = logf(th_ / bsah + 1e-16f);
    return valid;
}

static __device__ __forceinline__ const float* po_addr(
    int i, const float* __restrict__ p0, const float* __restrict__ p1,
    const float* __restrict__ p2, int cells0, int cells01)
{
    const float* p; int c;
    if (i < cells0)        { p = p0; c = i; }
    else if (i < cells01)  { p = p1; c = i - cells0; }
    else                   { p = p2; c = i - cells01; }
    return p + (size_t)c * CH + 4;
}

__global__ void __launch_bounds__(NT)
k_yolo(const float* __restrict__ p0, const float* __restrict__ p1,
       const float* __restrict__ p2, const float* __restrict__ tg,
       int B, int N, int cells0, int cells01, int total_cells,
       int SB, float* __restrict__ out)
{
    const int t    = threadIdx.x;
    const int b    = blockIdx.x;
    const int gtid = b * NT + t;
    const int nt3  = 3 * N;

    // ---- phase 0: target scatter (first SB blocks only; all wave-1) ----
    if (b < SB) {
        if (gtid < nt3) {
            int s = gtid / N, n = gtid % N;
            int key, cell, cid; float a0, a1, a2, a3;
            if (decode_target(tg, n, s, B, &key, &cell, &cid, &a0, &a1, &a2, &a3)) {
                atomicMax(&g_winner[key], (unsigned)(n + 1));
                atomicOr(&g_clsmask[key], 1u << cid);
            }
        }
        __threadfence();
        __syncthreads();
        if (t == 0) atomicAdd(&g_sem, 1u);
    }

    // ---- phase 1: no-obj baseline over all cells (ILP-4 grid-stride) ----
    float lbox = 0.f, lobj = 0.f, lcls = 0.f;
    const int stride = gridDim.x * NT;
    for (int i = gtid; i < total_cells; i += 4 * stride) {
        int i1 = i + stride, i2 = i + 2 * stride, i3 = i + 3 * stride;
        bool b1 = i1 < total_cells, b2 = i2 < total_cells, b3 = i3 < total_cells;
        float v0 = __ldg(po_addr(i, p0, p1, p2, cells0, cells01));
        float v1 = b1 ? __ldg(po_addr(i1, p0, p1, p2, cells0, cells01)) : 0.f;
        float v2 = b2 ? __ldg(po_addr(i2, p0, p1, p2, cells0, cells01)) : 0.f;
        float v3 = b3 ? __ldg(po_addr(i3, p0, p1, p2, cells0, cells01)) : 0.f;
        lobj += 0.5f * softplusf(v0);
        if (b1) lobj += 0.5f * softplusf(v1);
        if (b2) lobj += 0.5f * softplusf(v2);
        if (b3) lobj += 0.5f * softplusf(v3);
    }

    // ---- phase 2: obj-cell corrections (first SB blocks; doorbell wait) ----
    if (b < SB) {
        if (t == 0) {
            while (*((volatile unsigned int*)&g_sem) != (unsigned)SB)
                __nanosleep(64);
            __threadfence();
        }
        __syncthreads();
        if (gtid < nt3) {
            int s = gtid / N, n = gtid % N;
            int key, cell, cid; float txf, tyf, twt, tht;
            bool valid = decode_target(tg, n, s, B, &key, &cell, &cid,
                                       &txf, &tyf, &twt, &tht);
            if (valid && g_winner[key] == (unsigned)(n + 1)) {
                const float* p = ((s == 0) ? p0 : (s == 1) ? p1 : p2)
                                 + (size_t)cell * CH;
                float px = p[0], py = p[1], pw = p[2], ph = p[3], po = p[4];
                lbox += 5.0f * ((softplusf(px) - txf * px)
                              + (softplusf(py) - tyf * py)
                              + (pw - twt) * (pw - twt)
                              + (ph - tht) * (ph - tht));
                lobj += 0.5f * softplusf(po) - po;   // full-obj minus baseline
                unsigned m = g_clsmask[key];
                float cs = 0.f;
#pragma unroll
                for (int c = 0; c < NUM_CLASSES; c++) {
                    float pc = p[5 + c];
                    cs += softplusf(pc) - (((m >> c) & 1u) ? pc : 0.f);
                }
                lcls += cs;
                // self-clean: exactly one winner per key -> race-free reset
                g_winner[key]  = 0u;
                g_clsmask[key] = 0u;
            }
        }
    }

    // ---- phase 3: reduce and finalize ----
#pragma unroll
    for (int off = 16; off > 0; off >>= 1) {
        lbox += __shfl_down_sync(0xffffffffu, lbox, off);
        lobj += __shfl_down_sync(0xffffffffu, lobj, off);
        lcls += __shfl_down_sync(0xffffffffu, lcls, off);
    }
    __shared__ float sw[NT / 32][3];
    if ((t & 31) == 0) {
        sw[t >> 5][0] = lbox; sw[t >> 5][1] = lobj; sw[t >> 5][2] = lcls;
    }
    __syncthreads();
    if (t == 0) {
        float s0 = 0.f, s1 = 0.f, s2 = 0.f;
#pragma unroll
        for (int w = 0; w < NT / 32; w++) {
            s0 += sw[w][0]; s1 += sw[w][1]; s2 += sw[w][2];
        }
        atomicAdd(&g_acc[0], s0);
        atomicAdd(&g_acc[1], s1);
        atomicAdd(&g_acc[2], s2);
        __threadfence();
        unsigned old = atomicAdd(&g_done, 1u);
        if (old == gridDim.x - 1) {
            __threadfence();
            float bx = *((volatile float*)&g_acc[0]);
            float ob = *((volatile float*)&g_acc[1]);
            float cl = *((volatile float*)&g_acc[2]);
            out[0] = bx + ob + cl;
            out[1] = bx;
            out[2] = ob;
            out[3] = cl;
            // restore scratch for next graph replay
            g_acc[0] = 0.f; g_acc[1] = 0.f; g_acc[2] = 0.f;
            g_done = 0u;
            g_sem  = 0u;
        }
    }
}

extern "C" void kernel_launch(void* const* d_in, const int* in_sizes, int n_in,
                              void* d_out, int out_size) {
    const float* p0 = (const float*)d_in[0];  // pred_large  [B,3,13,13,30]
    const float* p1 = (const float*)d_in[1];  // pred_medium [B,3,26,26,30]
    const float* p2 = (const float*)d_in[2];  // pred_small  [B,3,52,52,30]
    const float* tg = (const float*)d_in[3];  // targets     [N,6]
    float* out = (float*)d_out;

    int B = in_sizes[0] / (3 * G0 * G0 * CH);
    int N = in_sizes[3] / 6;

    int cells0  = B * 3 * G0 * G0;
    int cells1  = B * 3 * G1 * G1;
    int cells2  = B * 3 * G2 * G2;
    int cells01 = cells0 + cells1;
    int total   = cells01 + cells2;

    int SB = (3 * N + NT - 1) / NT;   // scatter/correction blocks (24 for N=2048)

    k_yolo<<<NB, NT>>>(p0, p1, p2, tg, B, N,
                       cells0, cells01, total, SB, out);
}